// round 10
// baseline (speedup 1.0000x reference)
#include <cuda_runtime.h>
#include <math.h>

#define BATCH   64
#define MOL     50
#define PRO     500
#define HID     32
#define HEADS   8
#define N_MOL   (BATCH*MOL)      // 3200
#define N_PRO   (BATCH*PRO)      // 32000
#define N_ATOM  (N_MOL + N_PRO)  // 35200
#define PAIRS   (N_MOL*PRO)      // 1,600,000

#define MPB     5                  // mol rows per tile
#define PSPLIT  250                // pro atoms per tile
#define TPB     256
#define GPB     (MOL / MPB)        // 10 mol groups per batch
#define PAIR_BLOCKS (BATCH * GPB * (PRO / PSPLIT))   // 1280

// Per-atom layout (8 float4 = 32 floats):
//   [0,1]=sig raw halves, [2,3]=mu raw halves, [4,5]=exp(sig), [6,7]=exp(mu)
__device__ float g_mol_half[N_MOL * 32];
__device__ float g_pro_half[N_PRO * 32];
__device__ float g_acc[BATCH * HEADS];     // per-batch mu sums
__device__ unsigned int g_done;            // pair-block completion counter

__device__ __forceinline__ float elu1(float x) {
    return x > 0.0f ? x : (__expf(x) - 1.0f);
}

// ---------------------------------------------------------------------------
// Kernel 1: per-atom half projections + exp of halves, split-k.
// ---------------------------------------------------------------------------
__global__ void __launch_bounds__(TPB) precompute_kernel(
        const float* __restrict__ mol_feats,
        const float* __restrict__ pro_feats,
        const float* __restrict__ spatial,
        const float* __restrict__ W_sigma,
        const float* __restrict__ b_sigma,
        const float* __restrict__ W_mu,
        const float* __restrict__ b_mu) {
    __shared__ float4 s_W[256];   // [0,128)=W_sigma, [128,256)=W_mu
    for (int i = threadIdx.x; i < 256; i += TPB) {
        const float* src = (i < 128) ? W_sigma : W_mu;
        s_W[i] = ((const float4*)src)[i & 127];
    }
    __syncthreads();

    int t = blockIdx.x * TPB + threadIdx.x;
    if (t < BATCH * HEADS) g_acc[t] = 0.0f;
    if (t == 0) g_done = 0u;

    const int khalf = t & 1;
    const int pid   = t >> 1;
    const int which = (pid >= N_ATOM) ? 1 : 0;    // 0 = sigma, 1 = mu
    const int atom  = which ? (pid - N_ATOM) : pid;
    const float4* sW = s_W + which * 128;

    float4 x[4];
    float acc[HEADS];
    int wrow;
    float4* abase;

    if (atom < N_MOL) {
        const float4* f = (const float4*)(mol_feats + (size_t)atom * HID + khalf * 16);
        #pragma unroll
        for (int k = 0; k < 4; k++) x[k] = f[k];
        if (khalf == 0) {
            const float4* bsel = which ? (const float4*)b_mu : (const float4*)b_sigma;
            float4 b0 = bsel[0], b1 = bsel[1];
            acc[0] = b0.x; acc[1] = b0.y; acc[2] = b0.z; acc[3] = b0.w;
            acc[4] = b1.x; acc[5] = b1.y; acc[6] = b1.z; acc[7] = b1.w;
        } else {
            #pragma unroll
            for (int h = 0; h < HEADS; h++) acc[h] = 0.0f;
        }
        wrow = khalf * 16;
        abase = (float4*)(g_mol_half + (size_t)atom * 32);
    } else {
        int a = atom - N_MOL;
        const float4* f = (const float4*)(pro_feats + (size_t)a * HID + khalf * 16);
        const float4* s = (const float4*)(spatial   + (size_t)a * HID + khalf * 16);
        #pragma unroll
        for (int k = 0; k < 4; k++) {
            float4 fv = f[k], sv = s[k];
            x[k].x = fv.x * sv.x; x[k].y = fv.y * sv.y;
            x[k].z = fv.z * sv.z; x[k].w = fv.w * sv.w;
        }
        #pragma unroll
        for (int h = 0; h < HEADS; h++) acc[h] = 0.0f;
        wrow = HID + khalf * 16;
        abase = (float4*)(g_pro_half + (size_t)a * 32);
    }

    #pragma unroll
    for (int k = 0; k < 16; k++) {
        float xv = ((const float*)x)[k];
        float4 w0 = sW[(wrow + k) * 2 + 0];
        float4 w1 = sW[(wrow + k) * 2 + 1];
        acc[0] = fmaf(xv, w0.x, acc[0]); acc[1] = fmaf(xv, w0.y, acc[1]);
        acc[2] = fmaf(xv, w0.z, acc[2]); acc[3] = fmaf(xv, w0.w, acc[3]);
        acc[4] = fmaf(xv, w1.x, acc[4]); acc[5] = fmaf(xv, w1.y, acc[5]);
        acc[6] = fmaf(xv, w1.z, acc[6]); acc[7] = fmaf(xv, w1.w, acc[7]);
    }

    #pragma unroll
    for (int h = 0; h < HEADS; h++)
        acc[h] += __shfl_xor_sync(0xffffffffu, acc[h], 1);

    float v0 = acc[khalf * 4 + 0], v1 = acc[khalf * 4 + 1];
    float v2 = acc[khalf * 4 + 2], v3 = acc[khalf * 4 + 3];
    int rs = which * 2 + khalf;
    abase[rs]     = make_float4(v0, v1, v2, v3);
    abase[4 + rs] = make_float4(__expf(v0), __expf(v1), __expf(v2), __expf(v3));
}

// ---------------------------------------------------------------------------
// Kernel 2: per-pair sigma/mu. Branchless ELU via exp-product:
//   elu(m+p)+1.1 = fmax(m+p,0) + fmin(fma(em,ep,0.1), 1.1)
//   elu(m+p)+1.0 = fmax(m+p,0) + fmin(em*ep, 1.0)
// Two sweeps (sigma, then mu); mol halves hoisted to registers per sweep;
// per v-iteration: 2 LDS.128 feed 5 STG.128.
// ---------------------------------------------------------------------------
__global__ void __launch_bounds__(TPB, 4) pair_kernel(
        float* __restrict__ mu_out, float* __restrict__ sigma_out,
        const float* __restrict__ W1, const float* __restrict__ b1,
        const float* __restrict__ W2, const float* __restrict__ b2,
        float* __restrict__ y_out) {
    __shared__ float4 s_sig [PSPLIT * 2];
    __shared__ float4 s_mu  [PSPLIT * 2];
    __shared__ float4 s_esig[PSPLIT * 2];
    __shared__ float4 s_emu [PSPLIT * 2];
    __shared__ float4 s_molsig[MPB * 2], s_molmu[MPB * 2];
    __shared__ float4 s_molesig[MPB * 2], s_molemu[MPB * 2];
    __shared__ float  s_red[(TPB / 32) * 8];
    __shared__ int    s_last;

    const int tile  = blockIdx.x;
    const int ph    = tile & 1;
    const int g     = tile >> 1;
    const int batch = g / GPB;
    const int mg    = g % GPB;
    const int mol0  = batch * MOL + mg * MPB;
    const int pro0  = ph * PSPLIT;

    // Stage pro tile: 250 atoms x 8 float4, de-interleaved.
    const float4* gp = (const float4*)g_pro_half + ((size_t)batch * PRO + pro0) * 8;
    for (int i = threadIdx.x; i < PSPLIT * 8; i += TPB) {
        int a = i >> 3, c = i & 7;
        float4 val = gp[i];
        int s = a * 2 + (c & 1);
        switch (c >> 1) {
            case 0: s_sig[s]  = val; break;
            case 1: s_mu[s]   = val; break;
            case 2: s_esig[s] = val; break;
            default: s_emu[s] = val; break;
        }
    }
    const float4* gm = (const float4*)g_mol_half + (size_t)mol0 * 8;
    if (threadIdx.x < MPB * 8) {
        int a = threadIdx.x >> 3, c = threadIdx.x & 7;
        float4 val = gm[threadIdx.x];
        int s = a * 2 + (c & 1);
        switch (c >> 1) {
            case 0: s_molsig[s]  = val; break;
            case 1: s_molmu[s]   = val; break;
            case 2: s_molesig[s] = val; break;
            default: s_molemu[s] = val; break;
        }
    }
    __syncthreads();

    const int h = threadIdx.x & 1;   // parity fixed per thread (stride TPB even)
    // float4-unit base of this tile; row lm adds lm*PRO*2 (=1000) units.
    const size_t base = ((size_t)mol0 * PRO + pro0) * 2;

    // ================= sigma sweep =================
    {
        float4 ms[MPB], ems[MPB];
        #pragma unroll
        for (int lm = 0; lm < MPB; lm++) {
            ms[lm]  = s_molsig[lm * 2 + h];
            ems[lm] = s_molesig[lm * 2 + h];
        }
        float4* so = (float4*)sigma_out + base;
        for (int v = threadIdx.x; v < PSPLIT * 2; v += TPB) {
            const float4 ps  = s_sig[v];
            const float4 eps = s_esig[v];
            #pragma unroll
            for (int lm = 0; lm < MPB; lm++) {
                float4 sg;
                sg.x = fmaxf(ms[lm].x + ps.x, 0.f) + fminf(fmaf(ems[lm].x, eps.x, 0.1f), 1.1f);
                sg.y = fmaxf(ms[lm].y + ps.y, 0.f) + fminf(fmaf(ems[lm].y, eps.y, 0.1f), 1.1f);
                sg.z = fmaxf(ms[lm].z + ps.z, 0.f) + fminf(fmaf(ems[lm].z, eps.z, 0.1f), 1.1f);
                sg.w = fmaxf(ms[lm].w + ps.w, 0.f) + fminf(fmaf(ems[lm].w, eps.w, 0.1f), 1.1f);
                __stcs(so + lm * (PRO * 2) + v, sg);
            }
        }
    }

    // ================= mu sweep =================
    float4 acc = make_float4(0.f, 0.f, 0.f, 0.f);
    {
        float4 mm[MPB], emm[MPB];
        #pragma unroll
        for (int lm = 0; lm < MPB; lm++) {
            mm[lm]  = s_molmu[lm * 2 + h];
            emm[lm] = s_molemu[lm * 2 + h];
        }
        float4* mo = (float4*)mu_out + base;
        for (int v = threadIdx.x; v < PSPLIT * 2; v += TPB) {
            const float4 pm  = s_mu[v];
            const float4 epm = s_emu[v];
            #pragma unroll
            for (int lm = 0; lm < MPB; lm++) {
                float4 mv;
                mv.x = fmaxf(mm[lm].x + pm.x, 0.f) + fminf(emm[lm].x * epm.x, 1.0f);
                mv.y = fmaxf(mm[lm].y + pm.y, 0.f) + fminf(emm[lm].y * epm.y, 1.0f);
                mv.z = fmaxf(mm[lm].z + pm.z, 0.f) + fminf(emm[lm].z * epm.z, 1.0f);
                mv.w = fmaxf(mm[lm].w + pm.w, 0.f) + fminf(emm[lm].w * epm.w, 1.0f);
                __stcs(mo + lm * (PRO * 2) + v, mv);
                acc.x += mv.x; acc.y += mv.y; acc.z += mv.z; acc.w += mv.w;
            }
        }
    }

    // Reduce: same-parity lanes share head set; xor offsets >=2 preserve parity.
    #pragma unroll
    for (int off = 16; off >= 2; off >>= 1) {
        acc.x += __shfl_xor_sync(0xffffffffu, acc.x, off);
        acc.y += __shfl_xor_sync(0xffffffffu, acc.y, off);
        acc.z += __shfl_xor_sync(0xffffffffu, acc.z, off);
        acc.w += __shfl_xor_sync(0xffffffffu, acc.w, off);
    }
    int warp = threadIdx.x >> 5, lane = threadIdx.x & 31;
    if (lane < 2) {   // lane0: heads 0-3, lane1: heads 4-7
        s_red[warp * 8 + lane * 4 + 0] = acc.x;
        s_red[warp * 8 + lane * 4 + 1] = acc.y;
        s_red[warp * 8 + lane * 4 + 2] = acc.z;
        s_red[warp * 8 + lane * 4 + 3] = acc.w;
    }
    __syncthreads();
    if (threadIdx.x < 8) {
        float s = 0.f;
        #pragma unroll
        for (int w = 0; w < TPB / 32; w++) s += s_red[w * 8 + threadIdx.x];
        atomicAdd(&g_acc[batch * HEADS + threadIdx.x], s);
        __threadfence();
    }
    __syncthreads();

    if (threadIdx.x == 0) {
        unsigned int done = atomicAdd(&g_done, 1u);
        s_last = (done == PAIR_BLOCKS - 1) ? 1 : 0;
    }
    __syncthreads();
    if (s_last && threadIdx.x < BATCH) {
        int b = threadIdx.x;
        float v[HEADS];
        #pragma unroll
        for (int hh = 0; hh < HEADS; hh++)
            v[hh] = __ldcg(&g_acc[b * HEADS + hh]) * 0.001f;
        float y = __ldg(&b2[0]);
        #pragma unroll
        for (int jj = 0; jj < 2 * HEADS; jj++) {
            float hsum = __ldg(&b1[jj]);
            #pragma unroll
            for (int hh = 0; hh < HEADS; hh++)
                hsum = fmaf(v[hh], __ldg(&W1[hh * 2 * HEADS + jj]), hsum);
            y = fmaf(elu1(hsum), __ldg(&W2[jj]), y);
        }
        y_out[b] = y;
    }
}

extern "C" void kernel_launch(void* const* d_in, const int* in_sizes, int n_in,
                              void* d_out, int out_size) {
    const float* mol_feats = (const float*)d_in[0];
    const float* pro_feats = (const float*)d_in[1];
    const float* spatial   = (const float*)d_in[2];
    const float* W_sigma   = (const float*)d_in[3];
    const float* b_sigma   = (const float*)d_in[4];
    const float* W_mu      = (const float*)d_in[5];
    const float* b_mu      = (const float*)d_in[6];
    const float* W1        = (const float*)d_in[7];
    const float* b1        = (const float*)d_in[8];
    const float* W2        = (const float*)d_in[9];
    const float* b2        = (const float*)d_in[10];

    float* out       = (float*)d_out;
    float* mu_out    = out;
    float* sigma_out = out + (size_t)PAIRS * HEADS;
    float* y_out     = out + (size_t)2 * PAIRS * HEADS;

    int total_threads = 4 * N_ATOM;   // 140800 = 550 blocks exactly
    precompute_kernel<<<total_threads / TPB, TPB>>>(
        mol_feats, pro_feats, spatial, W_sigma, b_sigma, W_mu, b_mu);
    pair_kernel<<<PAIR_BLOCKS, TPB>>>(mu_out, sigma_out, W1, b1, W2, b2, y_out);
}

// round 11
// speedup vs baseline: 1.1263x; 1.1263x over previous
#include <cuda_runtime.h>
#include <math.h>

#define BATCH   64
#define MOL     50
#define PRO     500
#define HID     32
#define HEADS   8
#define N_MOL   (BATCH*MOL)      // 3200
#define N_PRO   (BATCH*PRO)      // 32000
#define N_ATOM  (N_MOL + N_PRO)  // 35200
#define PAIRS   (N_MOL*PRO)      // 1,600,000

#define MPB     5                  // mol rows per tile
#define PSPLIT  125                // pro atoms per tile
#define TPB     256
#define GPB     (MOL / MPB)        // 10
#define PTILES  (PRO / PSPLIT)     // 4
#define PAIR_BLOCKS (BATCH * GPB * PTILES)   // 2560

// Per-atom layout (8 float4 = 32 floats):
//   [0,1]=sig raw halves, [2,3]=mu raw halves, [4,5]=exp(sig), [6,7]=exp(mu)
__device__ float g_mol_half[N_MOL * 32];
__device__ float g_pro_half[N_PRO * 32];
__device__ float g_acc[BATCH * HEADS];
__device__ unsigned int g_done;

__device__ __forceinline__ float elu1(float x) {
    return x > 0.0f ? x : (__expf(x) - 1.0f);
}

// ---------------------------------------------------------------------------
// Kernel 1: per-atom half projections + exp of halves, split-k. (unchanged)
// ---------------------------------------------------------------------------
__global__ void __launch_bounds__(TPB) precompute_kernel(
        const float* __restrict__ mol_feats,
        const float* __restrict__ pro_feats,
        const float* __restrict__ spatial,
        const float* __restrict__ W_sigma,
        const float* __restrict__ b_sigma,
        const float* __restrict__ W_mu,
        const float* __restrict__ b_mu) {
    __shared__ float4 s_W[256];   // [0,128)=W_sigma, [128,256)=W_mu
    for (int i = threadIdx.x; i < 256; i += TPB) {
        const float* src = (i < 128) ? W_sigma : W_mu;
        s_W[i] = ((const float4*)src)[i & 127];
    }
    __syncthreads();

    int t = blockIdx.x * TPB + threadIdx.x;
    if (t < BATCH * HEADS) g_acc[t] = 0.0f;
    if (t == 0) g_done = 0u;

    const int khalf = t & 1;
    const int pid   = t >> 1;
    const int which = (pid >= N_ATOM) ? 1 : 0;    // 0 = sigma, 1 = mu
    const int atom  = which ? (pid - N_ATOM) : pid;
    const float4* sW = s_W + which * 128;

    float4 x[4];
    float acc[HEADS];
    int wrow;
    float4* abase;

    if (atom < N_MOL) {
        const float4* f = (const float4*)(mol_feats + (size_t)atom * HID + khalf * 16);
        #pragma unroll
        for (int k = 0; k < 4; k++) x[k] = f[k];
        if (khalf == 0) {
            const float4* bsel = which ? (const float4*)b_mu : (const float4*)b_sigma;
            float4 b0 = bsel[0], b1 = bsel[1];
            acc[0] = b0.x; acc[1] = b0.y; acc[2] = b0.z; acc[3] = b0.w;
            acc[4] = b1.x; acc[5] = b1.y; acc[6] = b1.z; acc[7] = b1.w;
        } else {
            #pragma unroll
            for (int h = 0; h < HEADS; h++) acc[h] = 0.0f;
        }
        wrow = khalf * 16;
        abase = (float4*)(g_mol_half + (size_t)atom * 32);
    } else {
        int a = atom - N_MOL;
        const float4* f = (const float4*)(pro_feats + (size_t)a * HID + khalf * 16);
        const float4* s = (const float4*)(spatial   + (size_t)a * HID + khalf * 16);
        #pragma unroll
        for (int k = 0; k < 4; k++) {
            float4 fv = f[k], sv = s[k];
            x[k].x = fv.x * sv.x; x[k].y = fv.y * sv.y;
            x[k].z = fv.z * sv.z; x[k].w = fv.w * sv.w;
        }
        #pragma unroll
        for (int h = 0; h < HEADS; h++) acc[h] = 0.0f;
        wrow = HID + khalf * 16;
        abase = (float4*)(g_pro_half + (size_t)a * 32);
    }

    #pragma unroll
    for (int k = 0; k < 16; k++) {
        float xv = ((const float*)x)[k];
        float4 w0 = sW[(wrow + k) * 2 + 0];
        float4 w1 = sW[(wrow + k) * 2 + 1];
        acc[0] = fmaf(xv, w0.x, acc[0]); acc[1] = fmaf(xv, w0.y, acc[1]);
        acc[2] = fmaf(xv, w0.z, acc[2]); acc[3] = fmaf(xv, w0.w, acc[3]);
        acc[4] = fmaf(xv, w1.x, acc[4]); acc[5] = fmaf(xv, w1.y, acc[5]);
        acc[6] = fmaf(xv, w1.z, acc[6]); acc[7] = fmaf(xv, w1.w, acc[7]);
    }

    #pragma unroll
    for (int h = 0; h < HEADS; h++)
        acc[h] += __shfl_xor_sync(0xffffffffu, acc[h], 1);

    float v0 = acc[khalf * 4 + 0], v1 = acc[khalf * 4 + 1];
    float v2 = acc[khalf * 4 + 2], v3 = acc[khalf * 4 + 3];
    int rs = which * 2 + khalf;
    abase[rs]     = make_float4(v0, v1, v2, v3);
    abase[4 + rs] = make_float4(__expf(v0), __expf(v1), __expf(v2), __expf(v3));
}

// ---------------------------------------------------------------------------
// Kernel 2: per-pair sigma/mu, branchless via exp-product:
//   elu(m+p)+1.1 = fmax(m+p,0) + fmin(fma(em,ep,0.1), 1.1)
//   elu(m+p)+1.0 = fmax(m+p,0) + fmin(em*ep, 1.0)
// One v-unit per thread (PSPLIT=125 -> 250 units < TPB); R6-style interleaved
// compute+store per lm; mol via broadcast LDS (not hoisted arrays).
// s_pro stride-10 float4/atom: conflict-free for all 4 access offsets.
// ---------------------------------------------------------------------------
__global__ void __launch_bounds__(TPB, 4) pair_kernel(
        float* __restrict__ mu_out, float* __restrict__ sigma_out,
        const float* __restrict__ W1, const float* __restrict__ b1,
        const float* __restrict__ W2, const float* __restrict__ b2,
        float* __restrict__ y_out) {
    __shared__ float4 s_pro[PSPLIT * 10];   // [atom*10 + c], c=0..7 used
    __shared__ float4 s_mol[MPB * 8];       // [lm*8 + c]
    __shared__ float  s_red[(TPB / 32) * 8];
    __shared__ int    s_last;

    const int tile  = blockIdx.x;
    const int pq    = tile & (PTILES - 1);       // pro quarter
    const int g     = tile >> 2;
    const int batch = g / GPB;
    const int mg    = g % GPB;
    const int mol0  = batch * MOL + mg * MPB;
    const int pro0  = pq * PSPLIT;

    // Stage pro tile: 125 atoms x 8 float4 -> stride 10.
    const float4* gp = (const float4*)g_pro_half + ((size_t)batch * PRO + pro0) * 8;
    for (int i = threadIdx.x; i < PSPLIT * 8; i += TPB) {
        int a = i >> 3, c = i & 7;
        s_pro[a * 10 + c] = gp[i];
    }
    const float4* gm = (const float4*)g_mol_half + (size_t)mol0 * 8;
    if (threadIdx.x < MPB * 8) s_mol[threadIdx.x] = gm[threadIdx.x];
    __syncthreads();

    float4 acc = make_float4(0.f, 0.f, 0.f, 0.f);
    const int tid = threadIdx.x;

    if (tid < PSPLIT * 2) {
        const int h = tid & 1;          // half (heads 0-3 or 4-7)
        const int j = tid >> 1;         // local pro atom
        const int pb = j * 10 + h;

        const float4 ps  = s_pro[pb + 0];
        const float4 pm  = s_pro[pb + 2];
        const float4 eps = s_pro[pb + 4];
        const float4 epm = s_pro[pb + 6];

        // float4-unit index of this thread's output within a row: v = tid.
        const size_t base = ((size_t)mol0 * PRO + pro0) * 2 + tid;
        float4* so = (float4*)sigma_out + base;
        float4* mo = (float4*)mu_out    + base;

        #pragma unroll
        for (int lm = 0; lm < MPB; lm++) {
            const float4 ms  = s_mol[lm * 8 + 0 + h];
            const float4 ems = s_mol[lm * 8 + 4 + h];
            float4 sg;
            sg.x = fmaxf(ms.x + ps.x, 0.f) + fminf(fmaf(ems.x, eps.x, 0.1f), 1.1f);
            sg.y = fmaxf(ms.y + ps.y, 0.f) + fminf(fmaf(ems.y, eps.y, 0.1f), 1.1f);
            sg.z = fmaxf(ms.z + ps.z, 0.f) + fminf(fmaf(ems.z, eps.z, 0.1f), 1.1f);
            sg.w = fmaxf(ms.w + ps.w, 0.f) + fminf(fmaf(ems.w, eps.w, 0.1f), 1.1f);
            __stcs(so + lm * (PRO * 2), sg);

            const float4 mm  = s_mol[lm * 8 + 2 + h];
            const float4 emm = s_mol[lm * 8 + 6 + h];
            float4 mv;
            mv.x = fmaxf(mm.x + pm.x, 0.f) + fminf(emm.x * epm.x, 1.0f);
            mv.y = fmaxf(mm.y + pm.y, 0.f) + fminf(emm.y * epm.y, 1.0f);
            mv.z = fmaxf(mm.z + pm.z, 0.f) + fminf(emm.z * epm.z, 1.0f);
            mv.w = fmaxf(mm.w + pm.w, 0.f) + fminf(emm.w * epm.w, 1.0f);
            __stcs(mo + lm * (PRO * 2), mv);

            acc.x += mv.x; acc.y += mv.y; acc.z += mv.z; acc.w += mv.w;
        }
    }

    // Reduce: same-parity lanes share head set; xor offsets >=2 preserve parity.
    #pragma unroll
    for (int off = 16; off >= 2; off >>= 1) {
        acc.x += __shfl_xor_sync(0xffffffffu, acc.x, off);
        acc.y += __shfl_xor_sync(0xffffffffu, acc.y, off);
        acc.z += __shfl_xor_sync(0xffffffffu, acc.z, off);
        acc.w += __shfl_xor_sync(0xffffffffu, acc.w, off);
    }
    int warp = threadIdx.x >> 5, lane = threadIdx.x & 31;
    if (lane < 2) {
        s_red[warp * 8 + lane * 4 + 0] = acc.x;
        s_red[warp * 8 + lane * 4 + 1] = acc.y;
        s_red[warp * 8 + lane * 4 + 2] = acc.z;
        s_red[warp * 8 + lane * 4 + 3] = acc.w;
    }
    __syncthreads();
    if (threadIdx.x < 8) {
        float s = 0.f;
        #pragma unroll
        for (int w = 0; w < TPB / 32; w++) s += s_red[w * 8 + threadIdx.x];
        atomicAdd(&g_acc[batch * HEADS + threadIdx.x], s);
        __threadfence();
    }
    __syncthreads();

    if (threadIdx.x == 0) {
        unsigned int done = atomicAdd(&g_done, 1u);
        s_last = (done == PAIR_BLOCKS - 1) ? 1 : 0;
    }
    __syncthreads();
    if (s_last && threadIdx.x < BATCH) {
        int b = threadIdx.x;
        float v[HEADS];
        #pragma unroll
        for (int hh = 0; hh < HEADS; hh++)
            v[hh] = __ldcg(&g_acc[b * HEADS + hh]) * 0.001f;
        float y = __ldg(&b2[0]);
        #pragma unroll
        for (int jj = 0; jj < 2 * HEADS; jj++) {
            float hsum = __ldg(&b1[jj]);
            #pragma unroll
            for (int hh = 0; hh < HEADS; hh++)
                hsum = fmaf(v[hh], __ldg(&W1[hh * 2 * HEADS + jj]), hsum);
            y = fmaf(elu1(hsum), __ldg(&W2[jj]), y);
        }
        y_out[b] = y;
    }
}

extern "C" void kernel_launch(void* const* d_in, const int* in_sizes, int n_in,
                              void* d_out, int out_size) {
    const float* mol_feats = (const float*)d_in[0];
    const float* pro_feats = (const float*)d_in[1];
    const float* spatial   = (const float*)d_in[2];
    const float* W_sigma   = (const float*)d_in[3];
    const float* b_sigma   = (const float*)d_in[4];
    const float* W_mu      = (const float*)d_in[5];
    const float* b_mu      = (const float*)d_in[6];
    const float* W1        = (const float*)d_in[7];
    const float* b1        = (const float*)d_in[8];
    const float* W2        = (const float*)d_in[9];
    const float* b2        = (const float*)d_in[10];

    float* out       = (float*)d_out;
    float* mu_out    = out;
    float* sigma_out = out + (size_t)PAIRS * HEADS;
    float* y_out     = out + (size_t)2 * PAIRS * HEADS;

    int total_threads = 4 * N_ATOM;   // 140800 = 550 blocks exactly
    precompute_kernel<<<total_threads / TPB, TPB>>>(
        mol_feats, pro_feats, spatial, W_sigma, b_sigma, W_mu, b_mu);
    pair_kernel<<<PAIR_BLOCKS, TPB>>>(mu_out, sigma_out, W1, b1, W2, b2, y_out);
}

// round 12
// speedup vs baseline: 1.1848x; 1.0520x over previous
#include <cuda_runtime.h>
#include <math.h>

#define BATCH   64
#define MOL     50
#define PRO     500
#define HID     32
#define HEADS   8
#define N_MOL   (BATCH*MOL)      // 3200
#define N_PRO   (BATCH*PRO)      // 32000
#define N_ATOM  (N_MOL + N_PRO)  // 35200
#define PAIRS   (N_MOL*PRO)      // 1,600,000

#define MPB     5                  // mol rows per tile
#define PSPLIT  250                // pro atoms per tile
#define TPB     256
#define GPB     (MOL / MPB)        // 10
#define NTILES  (BATCH * GPB * 2)  // 1280
#define GRID    592                // 4 blocks/SM x 148 SMs, all co-resident

// Per-atom layout (4 float4 = 16 floats): [0,1]=sig halves, [2,3]=mu halves
__device__ float g_mol_half[N_MOL * 16];
__device__ float g_pro_half[N_PRO * 16];
__device__ float g_acc[BATCH * HEADS];
__device__ unsigned int g_done;
__device__ unsigned int g_tile;
__device__ unsigned int g_bar;     // monotonic across graph replays

__device__ __forceinline__ float elu1(float x) {
    return x > 0.0f ? x : (__expf(x) - 1.0f);
}

// ---------------------------------------------------------------------------
// One persistent kernel: Phase A (per-atom projections) -> device barrier ->
// Phase B (work-stolen R6 pair tiles) -> Phase C (head MLP by last block).
// ---------------------------------------------------------------------------
__global__ void __launch_bounds__(TPB, 4) fused_kernel(
        const float* __restrict__ mol_feats,
        const float* __restrict__ pro_feats,
        const float* __restrict__ spatial,
        const float* __restrict__ W_sigma,
        const float* __restrict__ b_sigma,
        const float* __restrict__ W_mu,
        const float* __restrict__ b_mu,
        float* __restrict__ mu_out, float* __restrict__ sigma_out,
        const float* __restrict__ W1, const float* __restrict__ b1,
        const float* __restrict__ W2, const float* __restrict__ b2,
        float* __restrict__ y_out) {
    __shared__ float4 s_W[256];             // [0,128)=W_sigma, [128,256)=W_mu
    __shared__ float4 s_sig[PSPLIT * 2];    // [2*j + h] sigma halves
    __shared__ float4 s_mu [PSPLIT * 2];    // [2*j + h] mu halves
    __shared__ float4 s_molsig[MPB * 2], s_molmu[MPB * 2];
    __shared__ float  s_red[(TPB / 32) * 8];
    __shared__ int    s_tile;
    __shared__ int    s_last;

    const int tid = threadIdx.x;

    // ===================== Phase A: per-atom projections =====================
    for (int i = tid; i < 256; i += TPB) {
        const float* src = (i < 128) ? W_sigma : W_mu;
        s_W[i] = ((const float4*)src)[i & 127];
    }
    int t = blockIdx.x * TPB + tid;
    if (t < BATCH * HEADS) g_acc[t] = 0.0f;
    if (t == 0) { g_tile = 0u; g_done = 0u; }
    __syncthreads();

    if (t < 4 * N_ATOM) {
        const int khalf = t & 1;
        const int pid   = t >> 1;
        const int which = (pid >= N_ATOM) ? 1 : 0;    // 0 = sigma, 1 = mu
        const int atom  = which ? (pid - N_ATOM) : pid;
        const float4* sW = s_W + which * 128;

        float4 x[4];
        float acc[HEADS];
        int wrow;
        float4* abase;

        if (atom < N_MOL) {
            const float4* f = (const float4*)(mol_feats + (size_t)atom * HID + khalf * 16);
            #pragma unroll
            for (int k = 0; k < 4; k++) x[k] = f[k];
            if (khalf == 0) {
                const float4* bsel = which ? (const float4*)b_mu : (const float4*)b_sigma;
                float4 b0 = bsel[0], b1v = bsel[1];
                acc[0] = b0.x; acc[1] = b0.y; acc[2] = b0.z; acc[3] = b0.w;
                acc[4] = b1v.x; acc[5] = b1v.y; acc[6] = b1v.z; acc[7] = b1v.w;
            } else {
                #pragma unroll
                for (int h = 0; h < HEADS; h++) acc[h] = 0.0f;
            }
            wrow = khalf * 16;
            abase = (float4*)(g_mol_half + (size_t)atom * 16);
        } else {
            int a = atom - N_MOL;
            const float4* f = (const float4*)(pro_feats + (size_t)a * HID + khalf * 16);
            const float4* s = (const float4*)(spatial   + (size_t)a * HID + khalf * 16);
            #pragma unroll
            for (int k = 0; k < 4; k++) {
                float4 fv = f[k], sv = s[k];
                x[k].x = fv.x * sv.x; x[k].y = fv.y * sv.y;
                x[k].z = fv.z * sv.z; x[k].w = fv.w * sv.w;
            }
            #pragma unroll
            for (int h = 0; h < HEADS; h++) acc[h] = 0.0f;
            wrow = HID + khalf * 16;
            abase = (float4*)(g_pro_half + (size_t)a * 16);
        }

        #pragma unroll
        for (int k = 0; k < 16; k++) {
            float xv = ((const float*)x)[k];
            float4 w0 = sW[(wrow + k) * 2 + 0];
            float4 w1v = sW[(wrow + k) * 2 + 1];
            acc[0] = fmaf(xv, w0.x, acc[0]); acc[1] = fmaf(xv, w0.y, acc[1]);
            acc[2] = fmaf(xv, w0.z, acc[2]); acc[3] = fmaf(xv, w0.w, acc[3]);
            acc[4] = fmaf(xv, w1v.x, acc[4]); acc[5] = fmaf(xv, w1v.y, acc[5]);
            acc[6] = fmaf(xv, w1v.z, acc[6]); acc[7] = fmaf(xv, w1v.w, acc[7]);
        }

        #pragma unroll
        for (int h = 0; h < HEADS; h++)
            acc[h] += __shfl_xor_sync(0xffffffffu, acc[h], 1);

        float v0 = acc[khalf * 4 + 0], v1 = acc[khalf * 4 + 1];
        float v2 = acc[khalf * 4 + 2], v3 = acc[khalf * 4 + 3];
        abase[which * 2 + khalf] = make_float4(v0, v1, v2, v3);
    }

    // ===================== Device-wide barrier (all GRID blocks resident) ====
    __syncthreads();
    if (tid == 0) {
        __threadfence();                              // release this block's stores
        unsigned int tk  = atomicAdd(&g_bar, 1u);
        unsigned int tgt = tk - (tk % GRID) + GRID;   // next multiple of GRID
        while (*(volatile unsigned int*)&g_bar < tgt) __nanosleep(64);
        __threadfence();                              // acquire others' stores
    }
    __syncthreads();

    // ===================== Phase B: work-stolen pair tiles (R6 body) =========
    for (;;) {
        if (tid == 0) s_tile = (int)atomicAdd(&g_tile, 1u);
        __syncthreads();
        const int tile = s_tile;
        if (tile >= NTILES) break;

        const int ph    = tile & 1;
        const int g     = tile >> 1;
        const int batch = g / GPB;
        const int mg    = g % GPB;
        const int mol0  = batch * MOL + mg * MPB;
        const int pro0  = ph * PSPLIT;

        // Stage pro tile: 250 atoms x 4 float4, de-interleaved into sig/mu.
        const float4* gp = (const float4*)g_pro_half + ((size_t)batch * PRO + pro0) * 4;
        for (int i = tid; i < PSPLIT * 4; i += TPB) {
            int a = i >> 2, c = i & 3;
            float4 val = gp[i];
            if (c < 2) s_sig[a * 2 + c]       = val;
            else       s_mu [a * 2 + (c - 2)] = val;
        }
        const float4* gm = (const float4*)g_mol_half + (size_t)mol0 * 4;
        if (tid < MPB * 4) {
            int a = tid >> 2, c = tid & 3;
            float4 val = gm[tid];
            if (c < 2) s_molsig[a * 2 + c]       = val;
            else       s_molmu [a * 2 + (c - 2)] = val;
        }
        __syncthreads();

        float4 acc = make_float4(0.f, 0.f, 0.f, 0.f);
        const int h = tid & 1;   // stride TPB even -> parity fixed

        #pragma unroll
        for (int lm = 0; lm < MPB; lm++) {
            const size_t base = ((size_t)(mol0 + lm) * PRO + pro0) * 2;
            float4* so = (float4*)sigma_out + base;
            float4* mo = (float4*)mu_out    + base;

            const float4 ms = s_molsig[lm * 2 + h];
            const float4 mm = s_molmu [lm * 2 + h];

            for (int v = tid; v < PSPLIT * 2; v += TPB) {
                {
                    const float4 ps = s_sig[v];
                    float4 sg;
                    sg.x = elu1(ms.x + ps.x) + 1.1f;
                    sg.y = elu1(ms.y + ps.y) + 1.1f;
                    sg.z = elu1(ms.z + ps.z) + 1.1f;
                    sg.w = elu1(ms.w + ps.w) + 1.1f;
                    __stcs(so + v, sg);
                }
                {
                    const float4 pm = s_mu[v];
                    float4 mv;
                    mv.x = elu1(mm.x + pm.x) + 1.0f;
                    mv.y = elu1(mm.y + pm.y) + 1.0f;
                    mv.z = elu1(mm.z + pm.z) + 1.0f;
                    mv.w = elu1(mm.w + pm.w) + 1.0f;
                    __stcs(mo + v, mv);
                    acc.x += mv.x; acc.y += mv.y; acc.z += mv.z; acc.w += mv.w;
                }
            }
        }

        // Per-tile reduction (parity-preserving xor offsets >= 2).
        #pragma unroll
        for (int off = 16; off >= 2; off >>= 1) {
            acc.x += __shfl_xor_sync(0xffffffffu, acc.x, off);
            acc.y += __shfl_xor_sync(0xffffffffu, acc.y, off);
            acc.z += __shfl_xor_sync(0xffffffffu, acc.z, off);
            acc.w += __shfl_xor_sync(0xffffffffu, acc.w, off);
        }
        int warp = tid >> 5, lane = tid & 31;
        if (lane < 2) {
            s_red[warp * 8 + lane * 4 + 0] = acc.x;
            s_red[warp * 8 + lane * 4 + 1] = acc.y;
            s_red[warp * 8 + lane * 4 + 2] = acc.z;
            s_red[warp * 8 + lane * 4 + 3] = acc.w;
        }
        __syncthreads();
        if (tid < 8) {
            float s = 0.f;
            #pragma unroll
            for (int w = 0; w < TPB / 32; w++) s += s_red[w * 8 + tid];
            atomicAdd(&g_acc[batch * HEADS + tid], s);
            __threadfence();
        }
        __syncthreads();
    }

    // ===================== Phase C: head MLP by last block ===================
    if (tid == 0) {
        unsigned int done = atomicAdd(&g_done, 1u);
        s_last = (done == GRID - 1) ? 1 : 0;
    }
    __syncthreads();
    if (s_last && tid < BATCH) {
        int b = tid;
        float v[HEADS];
        #pragma unroll
        for (int hh = 0; hh < HEADS; hh++)
            v[hh] = __ldcg(&g_acc[b * HEADS + hh]) * 0.001f;
        float y = __ldg(&b2[0]);
        #pragma unroll
        for (int jj = 0; jj < 2 * HEADS; jj++) {
            float hsum = __ldg(&b1[jj]);
            #pragma unroll
            for (int hh = 0; hh < HEADS; hh++)
                hsum = fmaf(v[hh], __ldg(&W1[hh * 2 * HEADS + jj]), hsum);
            y = fmaf(elu1(hsum), __ldg(&W2[jj]), y);
        }
        y_out[b] = y;
    }
}

extern "C" void kernel_launch(void* const* d_in, const int* in_sizes, int n_in,
                              void* d_out, int out_size) {
    const float* mol_feats = (const float*)d_in[0];
    const float* pro_feats = (const float*)d_in[1];
    const float* spatial   = (const float*)d_in[2];
    const float* W_sigma   = (const float*)d_in[3];
    const float* b_sigma   = (const float*)d_in[4];
    const float* W_mu      = (const float*)d_in[5];
    const float* b_mu      = (const float*)d_in[6];
    const float* W1        = (const float*)d_in[7];
    const float* b1        = (const float*)d_in[8];
    const float* W2        = (const float*)d_in[9];
    const float* b2        = (const float*)d_in[10];

    float* out       = (float*)d_out;
    float* mu_out    = out;
    float* sigma_out = out + (size_t)PAIRS * HEADS;
    float* y_out     = out + (size_t)2 * PAIRS * HEADS;

    fused_kernel<<<GRID, TPB>>>(mol_feats, pro_feats, spatial,
                                W_sigma, b_sigma, W_mu, b_mu,
                                mu_out, sigma_out, W1, b1, W2, b2, y_out);
}

// round 13
// speedup vs baseline: 1.2285x; 1.0369x over previous
#include <cuda_runtime.h>
#include <math.h>

#define BATCH   64
#define MOL     50
#define PRO     500
#define HID     32
#define HEADS   8
#define N_MOL   (BATCH*MOL)      // 3200
#define N_PRO   (BATCH*PRO)      // 32000
#define N_ATOM  (N_MOL + N_PRO)  // 35200
#define PAIRS   (N_MOL*PRO)      // 1,600,000

#define MPB     5                  // mol rows per tile
#define PSPLIT  250                // pro atoms per tile
#define TPB     256
#define GPB     (MOL / MPB)        // 10
#define NTILES  (BATCH * GPB * 2)  // 1280
#define PGRID   740                // 5 blocks/SM x 148 SMs (work-stealing)

// Per-atom layout (4 float4 = 16 floats): [0,1]=sig halves, [2,3]=mu halves
__device__ float g_mol_half[N_MOL * 16];
__device__ float g_pro_half[N_PRO * 16];
__device__ float g_acc[BATCH * HEADS];
__device__ unsigned int g_done;    // completed tiles
__device__ unsigned int g_tile;    // steal counter

__device__ __forceinline__ float elu1(float x) {
    return x > 0.0f ? x : (__expf(x) - 1.0f);
}

// ---------------------------------------------------------------------------
// Kernel 1: per-atom half projections, split-k (R6 version).
// ---------------------------------------------------------------------------
__global__ void __launch_bounds__(TPB) precompute_kernel(
        const float* __restrict__ mol_feats,
        const float* __restrict__ pro_feats,
        const float* __restrict__ spatial,
        const float* __restrict__ W_sigma,
        const float* __restrict__ b_sigma,
        const float* __restrict__ W_mu,
        const float* __restrict__ b_mu) {
    __shared__ float4 s_W[256];   // [0,128)=W_sigma, [128,256)=W_mu
    for (int i = threadIdx.x; i < 256; i += TPB) {
        const float* src = (i < 128) ? W_sigma : W_mu;
        s_W[i] = ((const float4*)src)[i & 127];
    }
    __syncthreads();

    int t = blockIdx.x * TPB + threadIdx.x;
    if (t < BATCH * HEADS) g_acc[t] = 0.0f;
    if (t == 0) { g_tile = 0u; g_done = 0u; }

    const int khalf = t & 1;
    const int pid   = t >> 1;
    const int which = (pid >= N_ATOM) ? 1 : 0;    // 0 = sigma, 1 = mu
    const int atom  = which ? (pid - N_ATOM) : pid;
    const float4* sW = s_W + which * 128;

    float4 x[4];
    float acc[HEADS];
    int wrow;
    float4* abase;

    if (atom < N_MOL) {
        const float4* f = (const float4*)(mol_feats + (size_t)atom * HID + khalf * 16);
        #pragma unroll
        for (int k = 0; k < 4; k++) x[k] = f[k];
        if (khalf == 0) {
            const float4* bsel = which ? (const float4*)b_mu : (const float4*)b_sigma;
            float4 b0 = bsel[0], b1v = bsel[1];
            acc[0] = b0.x; acc[1] = b0.y; acc[2] = b0.z; acc[3] = b0.w;
            acc[4] = b1v.x; acc[5] = b1v.y; acc[6] = b1v.z; acc[7] = b1v.w;
        } else {
            #pragma unroll
            for (int h = 0; h < HEADS; h++) acc[h] = 0.0f;
        }
        wrow = khalf * 16;
        abase = (float4*)(g_mol_half + (size_t)atom * 16);
    } else {
        int a = atom - N_MOL;
        const float4* f = (const float4*)(pro_feats + (size_t)a * HID + khalf * 16);
        const float4* s = (const float4*)(spatial   + (size_t)a * HID + khalf * 16);
        #pragma unroll
        for (int k = 0; k < 4; k++) {
            float4 fv = f[k], sv = s[k];
            x[k].x = fv.x * sv.x; x[k].y = fv.y * sv.y;
            x[k].z = fv.z * sv.z; x[k].w = fv.w * sv.w;
        }
        #pragma unroll
        for (int h = 0; h < HEADS; h++) acc[h] = 0.0f;
        wrow = HID + khalf * 16;
        abase = (float4*)(g_pro_half + (size_t)a * 16);
    }

    #pragma unroll
    for (int k = 0; k < 16; k++) {
        float xv = ((const float*)x)[k];
        float4 w0 = sW[(wrow + k) * 2 + 0];
        float4 w1v = sW[(wrow + k) * 2 + 1];
        acc[0] = fmaf(xv, w0.x, acc[0]); acc[1] = fmaf(xv, w0.y, acc[1]);
        acc[2] = fmaf(xv, w0.z, acc[2]); acc[3] = fmaf(xv, w0.w, acc[3]);
        acc[4] = fmaf(xv, w1v.x, acc[4]); acc[5] = fmaf(xv, w1v.y, acc[5]);
        acc[6] = fmaf(xv, w1v.z, acc[6]); acc[7] = fmaf(xv, w1v.w, acc[7]);
    }

    #pragma unroll
    for (int h = 0; h < HEADS; h++)
        acc[h] += __shfl_xor_sync(0xffffffffu, acc[h], 1);

    float v0 = acc[khalf * 4 + 0], v1 = acc[khalf * 4 + 1];
    float v2 = acc[khalf * 4 + 2], v3 = acc[khalf * 4 + 3];
    abase[which * 2 + khalf] = make_float4(v0, v1, v2, v3);
}

// ---------------------------------------------------------------------------
// Kernel 2: R6 pair body, work-stealing over 1280 tiles at 5 blocks/SM.
// Head MLP run by the block that completes the final tile.
// ---------------------------------------------------------------------------
__global__ void __launch_bounds__(TPB, 5) pair_kernel(
        float* __restrict__ mu_out, float* __restrict__ sigma_out,
        const float* __restrict__ W1, const float* __restrict__ b1,
        const float* __restrict__ W2, const float* __restrict__ b2,
        float* __restrict__ y_out) {
    __shared__ float4 s_sig[PSPLIT * 2];    // [2*j + h] sigma halves
    __shared__ float4 s_mu [PSPLIT * 2];    // [2*j + h] mu halves
    __shared__ float4 s_molsig[MPB * 2], s_molmu[MPB * 2];
    __shared__ float  s_red[(TPB / 32) * 8];
    __shared__ int    s_tile;
    __shared__ int    s_last;

    const int tid = threadIdx.x;
    if (tid == 0) s_last = 0;
    __syncthreads();

    for (;;) {
        if (tid == 0) s_tile = (int)atomicAdd(&g_tile, 1u);
        __syncthreads();
        const int tile = s_tile;
        if (tile >= NTILES) break;

        const int ph    = tile & 1;
        const int g     = tile >> 1;
        const int batch = g / GPB;
        const int mg    = g % GPB;
        const int mol0  = batch * MOL + mg * MPB;
        const int pro0  = ph * PSPLIT;

        // Stage pro tile: 250 atoms x 4 float4, de-interleaved into sig/mu.
        const float4* gp = (const float4*)g_pro_half + ((size_t)batch * PRO + pro0) * 4;
        for (int i = tid; i < PSPLIT * 4; i += TPB) {
            int a = i >> 2, c = i & 3;
            float4 val = gp[i];
            if (c < 2) s_sig[a * 2 + c]       = val;
            else       s_mu [a * 2 + (c - 2)] = val;
        }
        const float4* gm = (const float4*)g_mol_half + (size_t)mol0 * 4;
        if (tid < MPB * 4) {
            int a = tid >> 2, c = tid & 3;
            float4 val = gm[tid];
            if (c < 2) s_molsig[a * 2 + c]       = val;
            else       s_molmu [a * 2 + (c - 2)] = val;
        }
        __syncthreads();

        float4 acc = make_float4(0.f, 0.f, 0.f, 0.f);
        const int h = tid & 1;   // stride TPB even -> parity fixed

        #pragma unroll
        for (int lm = 0; lm < MPB; lm++) {
            const size_t base = ((size_t)(mol0 + lm) * PRO + pro0) * 2;
            float4* so = (float4*)sigma_out + base;
            float4* mo = (float4*)mu_out    + base;

            const float4 ms = s_molsig[lm * 2 + h];
            const float4 mm = s_molmu [lm * 2 + h];

            for (int v = tid; v < PSPLIT * 2; v += TPB) {
                {
                    const float4 ps = s_sig[v];
                    float4 sg;
                    sg.x = elu1(ms.x + ps.x) + 1.1f;
                    sg.y = elu1(ms.y + ps.y) + 1.1f;
                    sg.z = elu1(ms.z + ps.z) + 1.1f;
                    sg.w = elu1(ms.w + ps.w) + 1.1f;
                    __stcs(so + v, sg);
                }
                {
                    const float4 pm = s_mu[v];
                    float4 mv;
                    mv.x = elu1(mm.x + pm.x) + 1.0f;
                    mv.y = elu1(mm.y + pm.y) + 1.0f;
                    mv.z = elu1(mm.z + pm.z) + 1.0f;
                    mv.w = elu1(mm.w + pm.w) + 1.0f;
                    __stcs(mo + v, mv);
                    acc.x += mv.x; acc.y += mv.y; acc.z += mv.z; acc.w += mv.w;
                }
            }
        }

        // Per-tile reduction (parity-preserving xor offsets >= 2).
        #pragma unroll
        for (int off = 16; off >= 2; off >>= 1) {
            acc.x += __shfl_xor_sync(0xffffffffu, acc.x, off);
            acc.y += __shfl_xor_sync(0xffffffffu, acc.y, off);
            acc.z += __shfl_xor_sync(0xffffffffu, acc.z, off);
            acc.w += __shfl_xor_sync(0xffffffffu, acc.w, off);
        }
        int warp = tid >> 5, lane = tid & 31;
        if (lane < 2) {
            s_red[warp * 8 + lane * 4 + 0] = acc.x;
            s_red[warp * 8 + lane * 4 + 1] = acc.y;
            s_red[warp * 8 + lane * 4 + 2] = acc.z;
            s_red[warp * 8 + lane * 4 + 3] = acc.w;
        }
        __syncthreads();
        if (tid < 8) {
            float s = 0.f;
            #pragma unroll
            for (int w = 0; w < TPB / 32; w++) s += s_red[w * 8 + tid];
            atomicAdd(&g_acc[batch * HEADS + tid], s);
        }
        __syncthreads();
        if (tid == 0) {
            __threadfence();
            unsigned int done = atomicAdd(&g_done, 1u);
            if (done == NTILES - 1) s_last = 1;
        }
        __syncthreads();
    }

    // Head MLP: run by the block that completed the final tile.
    if (s_last && tid < BATCH) {
        int b = tid;
        float v[HEADS];
        #pragma unroll
        for (int hh = 0; hh < HEADS; hh++)
            v[hh] = __ldcg(&g_acc[b * HEADS + hh]) * 0.001f;
        float y = __ldg(&b2[0]);
        #pragma unroll
        for (int jj = 0; jj < 2 * HEADS; jj++) {
            float hsum = __ldg(&b1[jj]);
            #pragma unroll
            for (int hh = 0; hh < HEADS; hh++)
                hsum = fmaf(v[hh], __ldg(&W1[hh * 2 * HEADS + jj]), hsum);
            y = fmaf(elu1(hsum), __ldg(&W2[jj]), y);
        }
        y_out[b] = y;
    }
}

extern "C" void kernel_launch(void* const* d_in, const int* in_sizes, int n_in,
                              void* d_out, int out_size) {
    const float* mol_feats = (const float*)d_in[0];
    const float* pro_feats = (const float*)d_in[1];
    const float* spatial   = (const float*)d_in[2];
    const float* W_sigma   = (const float*)d_in[3];
    const float* b_sigma   = (const float*)d_in[4];
    const float* W_mu      = (const float*)d_in[5];
    const float* b_mu      = (const float*)d_in[6];
    const float* W1        = (const float*)d_in[7];
    const float* b1        = (const float*)d_in[8];
    const float* W2        = (const float*)d_in[9];
    const float* b2        = (const float*)d_in[10];

    float* out       = (float*)d_out;
    float* mu_out    = out;
    float* sigma_out = out + (size_t)PAIRS * HEADS;
    float* y_out     = out + (size_t)2 * PAIRS * HEADS;

    int total_threads = 4 * N_ATOM;   // 140800 = 550 blocks exactly
    precompute_kernel<<<total_threads / TPB, TPB>>>(
        mol_feats, pro_feats, spatial, W_sigma, b_sigma, W_mu, b_mu);
    pair_kernel<<<PGRID, TPB>>>(mu_out, sigma_out, W1, b1, W2, b2, y_out);
}

// round 16
// speedup vs baseline: 1.2485x; 1.0162x over previous
#include <cuda_runtime.h>
#include <math.h>

#define BATCH   64
#define MOL     50
#define PRO     500
#define HID     32
#define HEADS   8
#define N_MOL   (BATCH*MOL)      // 3200
#define N_PRO   (BATCH*PRO)      // 32000
#define N_ATOM  (N_MOL + N_PRO)  // 35200
#define PAIRS   (N_MOL*PRO)      // 1,600,000

#define MPB     10                 // mol rows per tile
#define PSPLIT  250                // pro atoms per tile
#define TPB     256
#define GPB     (MOL / MPB)        // 5
#define NTILES  (BATCH * GPB * 2)  // 640
#define PAIR_BLOCKS NTILES         // one block per tile, single wave

// Per-atom layout (4 float4 = 16 floats): [0,1]=sig halves, [2,3]=mu halves
__device__ float g_mol_half[N_MOL * 16];
__device__ float g_pro_half[N_PRO * 16];
__device__ float g_acc[BATCH * HEADS];
__device__ unsigned int g_done;

__device__ __forceinline__ float elu1(float x) {
    return x > 0.0f ? x : (__expf(x) - 1.0f);
}

// ---------------------------------------------------------------------------
// Kernel 1: per-atom half projections, split-k (R6 version, unchanged).
// ---------------------------------------------------------------------------
__global__ void __launch_bounds__(TPB) precompute_kernel(
        const float* __restrict__ mol_feats,
        const float* __restrict__ pro_feats,
        const float* __restrict__ spatial,
        const float* __restrict__ W_sigma,
        const float* __restrict__ b_sigma,
        const float* __restrict__ W_mu,
        const float* __restrict__ b_mu) {
    __shared__ float4 s_W[256];   // [0,128)=W_sigma, [128,256)=W_mu
    for (int i = threadIdx.x; i < 256; i += TPB) {
        const float* src = (i < 128) ? W_sigma : W_mu;
        s_W[i] = ((const float4*)src)[i & 127];
    }
    __syncthreads();

    int t = blockIdx.x * TPB + threadIdx.x;
    if (t < BATCH * HEADS) g_acc[t] = 0.0f;
    if (t == 0) g_done = 0u;

    const int khalf = t & 1;
    const int pid   = t >> 1;
    const int which = (pid >= N_ATOM) ? 1 : 0;    // 0 = sigma, 1 = mu
    const int atom  = which ? (pid - N_ATOM) : pid;
    const float4* sW = s_W + which * 128;

    float4 x[4];
    float acc[HEADS];
    int wrow;
    float4* abase;

    if (atom < N_MOL) {
        const float4* f = (const float4*)(mol_feats + (size_t)atom * HID + khalf * 16);
        #pragma unroll
        for (int k = 0; k < 4; k++) x[k] = f[k];
        if (khalf == 0) {
            const float4* bsel = which ? (const float4*)b_mu : (const float4*)b_sigma;
            float4 b0 = bsel[0], b1v = bsel[1];
            acc[0] = b0.x; acc[1] = b0.y; acc[2] = b0.z; acc[3] = b0.w;
            acc[4] = b1v.x; acc[5] = b1v.y; acc[6] = b1v.z; acc[7] = b1v.w;
        } else {
            #pragma unroll
            for (int h = 0; h < HEADS; h++) acc[h] = 0.0f;
        }
        wrow = khalf * 16;
        abase = (float4*)(g_mol_half + (size_t)atom * 16);
    } else {
        int a = atom - N_MOL;
        const float4* f = (const float4*)(pro_feats + (size_t)a * HID + khalf * 16);
        const float4* s = (const float4*)(spatial   + (size_t)a * HID + khalf * 16);
        #pragma unroll
        for (int k = 0; k < 4; k++) {
            float4 fv = f[k], sv = s[k];
            x[k].x = fv.x * sv.x; x[k].y = fv.y * sv.y;
            x[k].z = fv.z * sv.z; x[k].w = fv.w * sv.w;
        }
        #pragma unroll
        for (int h = 0; h < HEADS; h++) acc[h] = 0.0f;
        wrow = HID + khalf * 16;
        abase = (float4*)(g_pro_half + (size_t)a * 16);
    }

    #pragma unroll
    for (int k = 0; k < 16; k++) {
        float xv = ((const float*)x)[k];
        float4 w0 = sW[(wrow + k) * 2 + 0];
        float4 w1v = sW[(wrow + k) * 2 + 1];
        acc[0] = fmaf(xv, w0.x, acc[0]); acc[1] = fmaf(xv, w0.y, acc[1]);
        acc[2] = fmaf(xv, w0.z, acc[2]); acc[3] = fmaf(xv, w0.w, acc[3]);
        acc[4] = fmaf(xv, w1v.x, acc[4]); acc[5] = fmaf(xv, w1v.y, acc[5]);
        acc[6] = fmaf(xv, w1v.z, acc[6]); acc[7] = fmaf(xv, w1v.w, acc[7]);
    }

    #pragma unroll
    for (int h = 0; h < HEADS; h++)
        acc[h] += __shfl_xor_sync(0xffffffffu, acc[h], 1);

    float v0 = acc[khalf * 4 + 0], v1 = acc[khalf * 4 + 1];
    float v2 = acc[khalf * 4 + 2], v3 = acc[khalf * 4 + 3];
    abase[which * 2 + khalf] = make_float4(v0, v1, v2, v3);
}

// ---------------------------------------------------------------------------
// Kernel 2: R6 pair body with MPB=10 -> 640 tiles, one block each (single
// wave at occ 5). Head MLP run by last block to finish (done counter).
// ---------------------------------------------------------------------------
__global__ void __launch_bounds__(TPB, 5) pair_kernel(
        float* __restrict__ mu_out, float* __restrict__ sigma_out,
        const float* __restrict__ W1, const float* __restrict__ b1,
        const float* __restrict__ W2, const float* __restrict__ b2,
        float* __restrict__ y_out) {
    __shared__ float4 s_sig[PSPLIT * 2];    // [2*j + h] sigma halves
    __shared__ float4 s_mu [PSPLIT * 2];    // [2*j + h] mu halves
    __shared__ float4 s_molsig[MPB * 2], s_molmu[MPB * 2];
    __shared__ float  s_red[(TPB / 32) * 8];
    __shared__ int    s_last;

    const int tid   = threadIdx.x;
    const int tile  = blockIdx.x;
    const int ph    = tile & 1;
    const int g     = tile >> 1;
    const int batch = g / GPB;
    const int mg    = g % GPB;
    const int mol0  = batch * MOL + mg * MPB;
    const int pro0  = ph * PSPLIT;

    // Stage pro tile: 250 atoms x 4 float4, de-interleaved into sig/mu.
    const float4* gp = (const float4*)g_pro_half + ((size_t)batch * PRO + pro0) * 4;
    for (int i = tid; i < PSPLIT * 4; i += TPB) {
        int a = i >> 2, c = i & 3;
        float4 val = gp[i];
        if (c < 2) s_sig[a * 2 + c]       = val;
        else       s_mu [a * 2 + (c - 2)] = val;
    }
    const float4* gm = (const float4*)g_mol_half + (size_t)mol0 * 4;
    if (tid < MPB * 4) {
        int a = tid >> 2, c = tid & 3;
        float4 val = gm[tid];
        if (c < 2) s_molsig[a * 2 + c]       = val;
        else       s_molmu [a * 2 + (c - 2)] = val;
    }
    __syncthreads();

    float4 acc = make_float4(0.f, 0.f, 0.f, 0.f);
    const int h = tid & 1;   // stride TPB even -> parity fixed per thread

    #pragma unroll
    for (int lm = 0; lm < MPB; lm++) {
        const size_t base = ((size_t)(mol0 + lm) * PRO + pro0) * 2;
        float4* so = (float4*)sigma_out + base;
        float4* mo = (float4*)mu_out    + base;

        const float4 ms = s_molsig[lm * 2 + h];
        const float4 mm = s_molmu [lm * 2 + h];

        for (int v = tid; v < PSPLIT * 2; v += TPB) {
            {
                const float4 ps = s_sig[v];
                float4 sg;
                sg.x = elu1(ms.x + ps.x) + 1.1f;
                sg.y = elu1(ms.y + ps.y) + 1.1f;
                sg.z = elu1(ms.z + ps.z) + 1.1f;
                sg.w = elu1(ms.w + ps.w) + 1.1f;
                __stcs(so + v, sg);
            }
            {
                const float4 pm = s_mu[v];
                float4 mv;
                mv.x = elu1(mm.x + pm.x) + 1.0f;
                mv.y = elu1(mm.y + pm.y) + 1.0f;
                mv.z = elu1(mm.z + pm.z) + 1.0f;
                mv.w = elu1(mm.w + pm.w) + 1.0f;
                __stcs(mo + v, mv);
                acc.x += mv.x; acc.y += mv.y; acc.z += mv.z; acc.w += mv.w;
            }
        }
    }

    // Per-tile reduction (parity-preserving xor offsets >= 2).
    #pragma unroll
    for (int off = 16; off >= 2; off >>= 1) {
        acc.x += __shfl_xor_sync(0xffffffffu, acc.x, off);
        acc.y += __shfl_xor_sync(0xffffffffu, acc.y, off);
        acc.z += __shfl_xor_sync(0xffffffffu, acc.z, off);
        acc.w += __shfl_xor_sync(0xffffffffu, acc.w, off);
    }
    int warp = tid >> 5, lane = tid & 31;
    if (lane < 2) {
        s_red[warp * 8 + lane * 4 + 0] = acc.x;
        s_red[warp * 8 + lane * 4 + 1] = acc.y;
        s_red[warp * 8 + lane * 4 + 2] = acc.z;
        s_red[warp * 8 + lane * 4 + 3] = acc.w;
    }
    __syncthreads();
    if (tid < 8) {
        float s = 0.f;
        #pragma unroll
        for (int w = 0; w < TPB / 32; w++) s += s_red[w * 8 + tid];
        atomicAdd(&g_acc[batch * HEADS + tid], s);
        __threadfence();
    }
    __syncthreads();

    if (tid == 0) {
        unsigned int done = atomicAdd(&g_done, 1u);
        s_last = (done == PAIR_BLOCKS - 1) ? 1 : 0;
    }
    __syncthreads();
    if (s_last && tid < BATCH) {
        int b = tid;
        float v[HEADS];
        #pragma unroll
        for (int hh = 0; hh < HEADS; hh++)
            v[hh] = __ldcg(&g_acc[b * HEADS + hh]) * 0.001f;
        float y = __ldg(&b2[0]);
        #pragma unroll
        for (int jj = 0; jj < 2 * HEADS; jj++) {
            float hsum = __ldg(&b1[jj]);
            #pragma unroll
            for (int hh = 0; hh < HEADS; hh++)
                hsum = fmaf(v[hh], __ldg(&W1[hh * 2 * HEADS + jj]), hsum);
            y = fmaf(elu1(hsum), __ldg(&W2[jj]), y);
        }
        y_out[b] = y;
    }
}

extern "C" void kernel_launch(void* const* d_in, const int* in_sizes, int n_in,
                              void* d_out, int out_size) {
    const float* mol_feats = (const float*)d_in[0];
    const float* pro_feats = (const float*)d_in[1];
    const float* spatial   = (const float*)d_in[2];
    const float* W_sigma   = (const float*)d_in[3];
    const float* b_sigma   = (const float*)d_in[4];
    const float* W_mu      = (const float*)d_in[5];
    const float* b_mu      = (const float*)d_in[6];
    const float* W1        = (const float*)d_in[7];
    const float* b1        = (const float*)d_in[8];
    const float* W2        = (const float*)d_in[9];
    const float* b2        = (const float*)d_in[10];

    float* out       = (float*)d_out;
    float* mu_out    = out;
    float* sigma_out = out + (size_t)PAIRS * HEADS;
    float* y_out     = out + (size_t)2 * PAIRS * HEADS;

    int total_threads = 4 * N_ATOM;   // 140800 = 550 blocks exactly
    precompute_kernel<<<total_threads / TPB, TPB>>>(
        mol_feats, pro_feats, spatial, W_sigma, b_sigma, W_mu, b_mu);
    pair_kernel<<<PAIR_BLOCKS, TPB>>>(mu_out, sigma_out, W1, b1, W2, b2, y_out);
}

// round 17
// speedup vs baseline: 1.2717x; 1.0186x over previous
#include <cuda_runtime.h>
#include <math.h>

#define BATCH   64
#define MOL     50
#define PRO     500
#define HID     32
#define HEADS   8
#define N_MOL   (BATCH*MOL)      // 3200
#define N_PRO   (BATCH*PRO)      // 32000
#define N_ATOM  (N_MOL + N_PRO)  // 35200
#define PAIRS   (N_MOL*PRO)      // 1,600,000

#define MPB     5                  // mol rows per tile (R6 config)
#define PSPLIT  250                // pro atoms per tile
#define TPB     256
#define GPB     (MOL / MPB)        // 10
#define PAIR_BLOCKS (BATCH * GPB * 2)   // 1280
#define NUNITS  (PSPLIT * 2)       // 500 float4 units per tile row

// Per-atom layout (4 float4 = 16 floats): [0,1]=sig halves, [2,3]=mu halves
__device__ float g_mol_half[N_MOL * 16];
__device__ float g_pro_half[N_PRO * 16];
__device__ float g_acc[BATCH * HEADS];
__device__ unsigned int g_done;

__device__ __forceinline__ float elu1(float x) {
    return x > 0.0f ? x : (__expf(x) - 1.0f);
}

// ---------------------------------------------------------------------------
// Kernel 1: per-atom half projections, split-k (unchanged, proven).
// ---------------------------------------------------------------------------
__global__ void __launch_bounds__(TPB) precompute_kernel(
        const float* __restrict__ mol_feats,
        const float* __restrict__ pro_feats,
        const float* __restrict__ spatial,
        const float* __restrict__ W_sigma,
        const float* __restrict__ b_sigma,
        const float* __restrict__ W_mu,
        const float* __restrict__ b_mu) {
    __shared__ float4 s_W[256];   // [0,128)=W_sigma, [128,256)=W_mu
    for (int i = threadIdx.x; i < 256; i += TPB) {
        const float* src = (i < 128) ? W_sigma : W_mu;
        s_W[i] = ((const float4*)src)[i & 127];
    }
    __syncthreads();

    int t = blockIdx.x * TPB + threadIdx.x;
    if (t < BATCH * HEADS) g_acc[t] = 0.0f;
    if (t == 0) g_done = 0u;

    const int khalf = t & 1;
    const int pid   = t >> 1;
    const int which = (pid >= N_ATOM) ? 1 : 0;    // 0 = sigma, 1 = mu
    const int atom  = which ? (pid - N_ATOM) : pid;
    const float4* sW = s_W + which * 128;

    float4 x[4];
    float acc[HEADS];
    int wrow;
    float4* abase;

    if (atom < N_MOL) {
        const float4* f = (const float4*)(mol_feats + (size_t)atom * HID + khalf * 16);
        #pragma unroll
        for (int k = 0; k < 4; k++) x[k] = f[k];
        if (khalf == 0) {
            const float4* bsel = which ? (const float4*)b_mu : (const float4*)b_sigma;
            float4 b0 = bsel[0], b1v = bsel[1];
            acc[0] = b0.x; acc[1] = b0.y; acc[2] = b0.z; acc[3] = b0.w;
            acc[4] = b1v.x; acc[5] = b1v.y; acc[6] = b1v.z; acc[7] = b1v.w;
        } else {
            #pragma unroll
            for (int h = 0; h < HEADS; h++) acc[h] = 0.0f;
        }
        wrow = khalf * 16;
        abase = (float4*)(g_mol_half + (size_t)atom * 16);
    } else {
        int a = atom - N_MOL;
        const float4* f = (const float4*)(pro_feats + (size_t)a * HID + khalf * 16);
        const float4* s = (const float4*)(spatial   + (size_t)a * HID + khalf * 16);
        #pragma unroll
        for (int k = 0; k < 4; k++) {
            float4 fv = f[k], sv = s[k];
            x[k].x = fv.x * sv.x; x[k].y = fv.y * sv.y;
            x[k].z = fv.z * sv.z; x[k].w = fv.w * sv.w;
        }
        #pragma unroll
        for (int h = 0; h < HEADS; h++) acc[h] = 0.0f;
        wrow = HID + khalf * 16;
        abase = (float4*)(g_pro_half + (size_t)a * 16);
    }

    #pragma unroll
    for (int k = 0; k < 16; k++) {
        float xv = ((const float*)x)[k];
        float4 w0 = sW[(wrow + k) * 2 + 0];
        float4 w1v = sW[(wrow + k) * 2 + 1];
        acc[0] = fmaf(xv, w0.x, acc[0]); acc[1] = fmaf(xv, w0.y, acc[1]);
        acc[2] = fmaf(xv, w0.z, acc[2]); acc[3] = fmaf(xv, w0.w, acc[3]);
        acc[4] = fmaf(xv, w1v.x, acc[4]); acc[5] = fmaf(xv, w1v.y, acc[5]);
        acc[6] = fmaf(xv, w1v.z, acc[6]); acc[7] = fmaf(xv, w1v.w, acc[7]);
    }

    #pragma unroll
    for (int h = 0; h < HEADS; h++)
        acc[h] += __shfl_xor_sync(0xffffffffu, acc[h], 1);

    float v0 = acc[khalf * 4 + 0], v1 = acc[khalf * 4 + 1];
    float v2 = acc[khalf * 4 + 2], v3 = acc[khalf * 4 + 3];
    abase[which * 2 + khalf] = make_float4(v0, v1, v2, v3);
}

// ---------------------------------------------------------------------------
// Kernel 2: R6 pair body with explicit two-unit software pipelining.
// Each thread owns units u0=tid and u1=tid+256 (same parity); per lm the
// two pro LDS issue back-to-back and 8 independent ELUs fill the latency.
// ---------------------------------------------------------------------------
__global__ void __launch_bounds__(TPB, 5) pair_kernel(
        float* __restrict__ mu_out, float* __restrict__ sigma_out,
        const float* __restrict__ W1, const float* __restrict__ b1,
        const float* __restrict__ W2, const float* __restrict__ b2,
        float* __restrict__ y_out) {
    __shared__ float4 s_sig[NUNITS];        // [2*j + h] sigma halves
    __shared__ float4 s_mu [NUNITS];        // [2*j + h] mu halves
    __shared__ float4 s_molsig[MPB * 2], s_molmu[MPB * 2];
    __shared__ float  s_red[(TPB / 32) * 8];
    __shared__ int    s_last;

    const int tid   = threadIdx.x;
    const int tile  = blockIdx.x;
    const int ph    = tile & 1;
    const int g     = tile >> 1;
    const int batch = g / GPB;
    const int mg    = g % GPB;
    const int mol0  = batch * MOL + mg * MPB;
    const int pro0  = ph * PSPLIT;

    // Stage pro tile: 250 atoms x 4 float4, de-interleaved into sig/mu.
    const float4* gp = (const float4*)g_pro_half + ((size_t)batch * PRO + pro0) * 4;
    for (int i = tid; i < PSPLIT * 4; i += TPB) {
        int a = i >> 2, c = i & 3;
        float4 val = gp[i];
        if (c < 2) s_sig[a * 2 + c]       = val;
        else       s_mu [a * 2 + (c - 2)] = val;
    }
    const float4* gm = (const float4*)g_mol_half + (size_t)mol0 * 4;
    if (tid < MPB * 4) {
        int a = tid >> 2, c = tid & 3;
        float4 val = gm[tid];
        if (c < 2) s_molsig[a * 2 + c]       = val;
        else       s_molmu [a * 2 + (c - 2)] = val;
    }
    __syncthreads();

    float4 acc = make_float4(0.f, 0.f, 0.f, 0.f);
    const int h    = tid & 1;               // parity (same for u0 and u1)
    const int u0   = tid;
    const int u1   = tid + TPB;
    const bool act = (u1 < NUNITS);         // tid < 244

    #pragma unroll
    for (int lm = 0; lm < MPB; lm++) {
        const size_t base = ((size_t)(mol0 + lm) * PRO + pro0) * 2;
        float4* so = (float4*)sigma_out + base;
        float4* mo = (float4*)mu_out    + base;

        // ---- sigma phase: both units ----
        {
            const float4 ms  = s_molsig[lm * 2 + h];
            const float4 ps0 = s_sig[u0];
            float4 ps1;
            if (act) ps1 = s_sig[u1];
            float4 sg0, sg1;
            sg0.x = elu1(ms.x + ps0.x) + 1.1f;
            sg0.y = elu1(ms.y + ps0.y) + 1.1f;
            sg0.z = elu1(ms.z + ps0.z) + 1.1f;
            sg0.w = elu1(ms.w + ps0.w) + 1.1f;
            if (act) {
                sg1.x = elu1(ms.x + ps1.x) + 1.1f;
                sg1.y = elu1(ms.y + ps1.y) + 1.1f;
                sg1.z = elu1(ms.z + ps1.z) + 1.1f;
                sg1.w = elu1(ms.w + ps1.w) + 1.1f;
            }
            __stcs(so + u0, sg0);
            if (act) __stcs(so + u1, sg1);
        }
        // ---- mu phase: both units ----
        {
            const float4 mm  = s_molmu[lm * 2 + h];
            const float4 pm0 = s_mu[u0];
            float4 pm1;
            if (act) pm1 = s_mu[u1];
            float4 mv0, mv1;
            mv0.x = elu1(mm.x + pm0.x) + 1.0f;
            mv0.y = elu1(mm.y + pm0.y) + 1.0f;
            mv0.z = elu1(mm.z + pm0.z) + 1.0f;
            mv0.w = elu1(mm.w + pm0.w) + 1.0f;
            if (act) {
                mv1.x = elu1(mm.x + pm1.x) + 1.0f;
                mv1.y = elu1(mm.y + pm1.y) + 1.0f;
                mv1.z = elu1(mm.z + pm1.z) + 1.0f;
                mv1.w = elu1(mm.w + pm1.w) + 1.0f;
            }
            __stcs(mo + u0, mv0);
            acc.x += mv0.x; acc.y += mv0.y; acc.z += mv0.z; acc.w += mv0.w;
            if (act) {
                __stcs(mo + u1, mv1);
                acc.x += mv1.x; acc.y += mv1.y; acc.z += mv1.z; acc.w += mv1.w;
            }
        }
    }

    // Per-tile reduction (parity-preserving xor offsets >= 2).
    #pragma unroll
    for (int off = 16; off >= 2; off >>= 1) {
        acc.x += __shfl_xor_sync(0xffffffffu, acc.x, off);
        acc.y += __shfl_xor_sync(0xffffffffu, acc.y, off);
        acc.z += __shfl_xor_sync(0xffffffffu, acc.z, off);
        acc.w += __shfl_xor_sync(0xffffffffu, acc.w, off);
    }
    int warp = tid >> 5, lane = tid & 31;
    if (lane < 2) {
        s_red[warp * 8 + lane * 4 + 0] = acc.x;
        s_red[warp * 8 + lane * 4 + 1] = acc.y;
        s_red[warp * 8 + lane * 4 + 2] = acc.z;
        s_red[warp * 8 + lane * 4 + 3] = acc.w;
    }
    __syncthreads();
    if (tid < 8) {
        float s = 0.f;
        #pragma unroll
        for (int w = 0; w < TPB / 32; w++) s += s_red[w * 8 + tid];
        atomicAdd(&g_acc[batch * HEADS + tid], s);
        __threadfence();
    }
    __syncthreads();

    if (tid == 0) {
        unsigned int done = atomicAdd(&g_done, 1u);
        s_last = (done == PAIR_BLOCKS - 1) ? 1 : 0;
    }
    __syncthreads();
    if (s_last && tid < BATCH) {
        int b = tid;
        float v[HEADS];
        #pragma unroll
        for (int hh = 0; hh < HEADS; hh++)
            v[hh] = __ldcg(&g_acc[b * HEADS + hh]) * 0.001f;
        float y = __ldg(&b2[0]);
        #pragma unroll
        for (int jj = 0; jj < 2 * HEADS; jj++) {
            float hsum = __ldg(&b1[jj]);
            #pragma unroll
            for (int hh = 0; hh < HEADS; hh++)
                hsum = fmaf(v[hh], __ldg(&W1[hh * 2 * HEADS + jj]), hsum);
            y = fmaf(elu1(hsum), __ldg(&W2[jj]), y);
        }
        y_out[b] = y;
    }
}

extern "C" void kernel_launch(void* const* d_in, const int* in_sizes, int n_in,
                              void* d_out, int out_size) {
    const float* mol_feats = (const float*)d_in[0];
    const float* pro_feats = (const float*)d_in[1];
    const float* spatial   = (const float*)d_in[2];
    const float* W_sigma   = (const float*)d_in[3];
    const float* b_sigma   = (const float*)d_in[4];
    const float* W_mu      = (const float*)d_in[5];
    const float* b_mu      = (const float*)d_in[6];
    const float* W1        = (const float*)d_in[7];
    const float* b1        = (const float*)d_in[8];
    const float* W2        = (const float*)d_in[9];
    const float* b2        = (const float*)d_in[10];

    float* out       = (float*)d_out;
    float* mu_out    = out;
    float* sigma_out = out + (size_t)PAIRS * HEADS;
    float* y_out     = out + (size_t)2 * PAIRS * HEADS;

    int total_threads = 4 * N_ATOM;   // 140800 = 550 blocks exactly
    precompute_kernel<<<total_threads / TPB, TPB>>>(
        mol_feats, pro_feats, spatial, W_sigma, b_sigma, W_mu, b_mu);
    pair_kernel<<<PAIR_BLOCKS, TPB>>>(mu_out, sigma_out, W1, b1, W2, b2, y_out);
}